// round 1
// baseline (speedup 1.0000x reference)
#include <cuda_runtime.h>

// Problem constants
#define C_   192
#define HW_  4096
#define W_   64
#define NOUT 36864   // C*C per (b,off)

// ---------------------------------------------------------------------------
// packed fp32x2 FMA (Blackwell): d = a*b + c on float pairs
// ---------------------------------------------------------------------------
__device__ __forceinline__ unsigned long long ffma2(unsigned long long a,
                                                    unsigned long long b,
                                                    unsigned long long c) {
    unsigned long long d;
    asm("fma.rn.f32x2 %0, %1, %2, %3;" : "=l"(d) : "l"(a), "l"(b), "l"(c));
    return d;
}

union U64F2 { unsigned long long u; float2 f; };

// ---------------------------------------------------------------------------
// GEMM kernel: per (b, offset): co[c][d] = sum_p x[b,c,p] * xshift[b,d,p]
// Grid: (3, 3, 80)  ->  (n-tile, m-tile, b*5+off).  Block: 128 threads.
// BM=BN=64, Kt=32, thread tile 8x4 (ty 0..7 -> 8 rows, tx 0..15 -> 4 cols)
// A stored duplicated per channel ({a,a} pairs) so f32x2 needs no packing.
// Both smem tiles XOR-swizzled by (k>>2) for conflict-light stores.
// ---------------------------------------------------------------------------
__global__ __launch_bounds__(128) void cofe_gemm(const float* __restrict__ x,
                                                 float* __restrict__ out) {
    __shared__ float As2[32 * 136];   // [k][dup-c], pitch 136 floats (68 f2 units)
    __shared__ float Bs[32 * 68];     // [k][n],     pitch 68 floats

    const int tid = threadIdx.x;
    const int tx  = tid & 15;   // n group
    const int ty  = tid >> 4;   // m group
    const int kq  = tid & 7;    // k quad (loader)
    const int cl  = tid >> 3;   // 0..15  channel (loader)

    const int bz  = blockIdx.z;
    const int b   = bz / 5;
    const int off = bz % 5;
    const int dy  = (off < 3) ? -1 : 0;
    const int dx  = (off < 3) ? (off - 1) : (off - 4);
    const int cA0 = blockIdx.y * 64;
    const int cB0 = blockIdx.x * 64;
    const float* xb = x + (size_t)b * C_ * HW_;

    unsigned long long acc[8][2];
#pragma unroll
    for (int i = 0; i < 8; i++) { acc[i][0] = 0ull; acc[i][1] = 0ull; }

    for (int kbase = 0; kbase < HW_; kbase += 32) {
        // ---- fill A tile (center), duplicated pairs, swizzled ----
#pragma unroll
        for (int g = 0; g < 4; g++) {
            int c = cl + g * 16;
            float4 v = *reinterpret_cast<const float4*>(
                xb + (size_t)(cA0 + c) * HW_ + kbase + kq * 4);
            float va[4] = {v.x, v.y, v.z, v.w};
#pragma unroll
            for (int j = 0; j < 4; j++) {
                int k  = kq * 4 + j;
                int us = c ^ (kq << 2);  // swizzle key = k>>2 = kq
                *(reinterpret_cast<float2*>(As2 + k * 136) + us) =
                    make_float2(va[j], va[j]);
            }
        }
        // ---- fill B tile (edge-clamped shifted side), swizzled ----
#pragma unroll
        for (int g = 0; g < 4; g++) {
            int c = cl + g * 16;
            const float* row = xb + (size_t)(cB0 + c) * HW_;
#pragma unroll
            for (int j = 0; j < 4; j++) {
                int k  = kq * 4 + j;
                int kg = kbase + k;
                int yy = kg >> 6;
                int xx = kg & 63;
                int py = yy + dy; py = (py < 0) ? 0 : py;
                int px = xx + dx; px = (px < 0) ? 0 : ((px > 63) ? 63 : px);
                int bs = ((c >> 2) ^ kq) * 4 + (c & 3);
                Bs[k * 68 + bs] = row[py * 64 + px];
            }
        }
        __syncthreads();

        // ---- inner product: 16 ffma2 per k per thread ----
#pragma unroll
        for (int k = 0; k < 32; k++) {
            const int sw = (k >> 2) << 2;   // swizzle key for this k
            unsigned long long ad[8];
#pragma unroll
            for (int t = 0; t < 4; t++) {
                int u = (ty * 8 + 2 * t) ^ sw;     // even float2-unit index
                ulonglong2 av = *reinterpret_cast<const ulonglong2*>(
                    As2 + k * 136 + 2 * u);
                ad[2 * t]     = av.x;   // {a[m+2t],   a[m+2t]}
                ad[2 * t + 1] = av.y;   // {a[m+2t+1], a[m+2t+1]}
            }
            int bb = ((tx ^ (k >> 2)) << 2);
            ulonglong2 bv = *reinterpret_cast<const ulonglong2*>(
                Bs + k * 68 + bb);      // {b0,b1},{b2,b3}
#pragma unroll
            for (int i = 0; i < 8; i++) {
                acc[i][0] = ffma2(ad[i], bv.x, acc[i][0]);
                acc[i][1] = ffma2(ad[i], bv.y, acc[i][1]);
            }
        }
        __syncthreads();
    }

    // ---- epilogue: write raw co tile ----
    float* o = out + (size_t)bz * NOUT;
#pragma unroll
    for (int i = 0; i < 8; i++) {
        int c = cA0 + ty * 8 + i;
        U64F2 v0, v1;
        v0.u = acc[i][0];
        v1.u = acc[i][1];
        float4 w = make_float4(v0.f.x, v0.f.y, v1.f.x, v1.f.y);
        *reinterpret_cast<float4*>(o + (size_t)c * C_ + cB0 + tx * 4) = w;
    }
}

// ---------------------------------------------------------------------------
// Normalization: per (b,off), L2-normalize the 36864-vector in place.
// Grid: 80 blocks x 256 threads.
// ---------------------------------------------------------------------------
__global__ __launch_bounds__(256) void cofe_norm(float* __restrict__ out) {
    float* o = out + (size_t)blockIdx.x * NOUT;
    float4* o4 = reinterpret_cast<float4*>(o);
    const int tid = threadIdx.x;

    float s = 0.f;
#pragma unroll 4
    for (int i = tid; i < NOUT / 4; i += 256) {
        float4 v = o4[i];
        s += v.x * v.x + v.y * v.y + v.z * v.z + v.w * v.w;
    }
    __shared__ float red[8];
#pragma unroll
    for (int d = 16; d > 0; d >>= 1) s += __shfl_xor_sync(0xffffffffu, s, d);
    if ((tid & 31) == 0) red[tid >> 5] = s;
    __syncthreads();
    if (tid < 32) {
        float v = (tid < 8) ? red[tid] : 0.f;
#pragma unroll
        for (int d = 4; d > 0; d >>= 1) v += __shfl_xor_sync(0xffffffffu, v, d);
        if (tid == 0) red[0] = v;
    }
    __syncthreads();
    const float scale = 1.0f / fmaxf(sqrtf(red[0]), 1e-12f);

#pragma unroll 4
    for (int i = tid; i < NOUT / 4; i += 256) {
        float4 v = o4[i];
        v.x *= scale; v.y *= scale; v.z *= scale; v.w *= scale;
        o4[i] = v;
    }
}

// ---------------------------------------------------------------------------
extern "C" void kernel_launch(void* const* d_in, const int* in_sizes, int n_in,
                              void* d_out, int out_size) {
    const float* x = (const float*)d_in[0];
    float* out = (float*)d_out;
    dim3 grid(3, 3, 80);
    cofe_gemm<<<grid, 128>>>(x, out);
    cofe_norm<<<80, 256>>>(out);
}

// round 3
// speedup vs baseline: 4.7622x; 4.7622x over previous
#include <cuda_runtime.h>
#include <cstdint>

#define B_    16
#define C_    192
#define HW_   4096
#define NOUT  (C_*C_)
#define KSPLIT 4
#define KPER   (HW_/KSPLIT)     // 1024
#define NKT    (KPER/32)        // 32 k-tiles per CTA

// partial accumulators: [split][g=b*5+off][c][d]
__device__ float g_part[(size_t)KSPLIT * 80 * NOUT];

// ---------------------------------------------------------------------------
__device__ __forceinline__ uint32_t smem_u32(const void* p) {
    uint32_t a;
    asm("{ .reg .u64 t; cvta.to.shared.u64 t, %1; cvt.u32.u64 %0, t; }" : "=r"(a) : "l"(p));
    return a;
}
__device__ __forceinline__ void cp_async16(uint32_t dst, const void* src) {
    asm volatile("cp.async.cg.shared.global [%0], [%1], 16;" :: "r"(dst), "l"(src) : "memory");
}
__device__ __forceinline__ void cp_commit() {
    asm volatile("cp.async.commit_group;" ::: "memory");
}
template <int N>
__device__ __forceinline__ void cp_wait() {
    asm volatile("cp.async.wait_group %0;" :: "n"(N) : "memory");
}
__device__ __forceinline__ void ldsm4(uint32_t* r, uint32_t addr) {
    asm volatile("ldmatrix.sync.aligned.m8n8.x4.shared.b16 {%0,%1,%2,%3}, [%4];"
                 : "=r"(r[0]), "=r"(r[1]), "=r"(r[2]), "=r"(r[3]) : "r"(addr));
}
__device__ __forceinline__ uint32_t to_tf32(uint32_t v) {
    uint32_t o;
    asm("cvt.rna.tf32.f32 %0, %1;" : "=r"(o) : "f"(__uint_as_float(v)));
    return o;
}
__device__ __forceinline__ void mma8(float* d, const uint32_t* a, const uint32_t* b) {
    asm volatile("mma.sync.aligned.m16n8k8.row.col.f32.tf32.tf32.f32 "
                 "{%0,%1,%2,%3}, {%4,%5,%6,%7}, {%8,%9}, {%0,%1,%2,%3};"
                 : "+f"(d[0]), "+f"(d[1]), "+f"(d[2]), "+f"(d[3])
                 : "r"(a[0]), "r"(a[1]), "r"(a[2]), "r"(a[3]), "r"(b[0]), "r"(b[1]));
}
__device__ __forceinline__ void sts32(uint32_t addr, float v) {
    asm volatile("st.shared.f32 [%0], %1;" :: "r"(addr), "f"(v) : "memory");
}

// ---------------------------------------------------------------------------
// GEMM: CTA tile M=96 (A rows), N=192 (all B rows), K=1024 (one split).
// 128 threads = 4 warps (2x2), warp tile 48x96. tf32 mma.sync m16n8k8.
// A = x[b, cA0+0..95, :]  (k-contiguous), B = edge-clamp-shifted x[b, 0..191, :].
// smem per stage: A 96x128B + B 192x128B = 36864B, 2 stages.
// swizzle: byte(row, chunk, j) = row*128 + ((chunk ^ (row&7))<<4) + j*4
// ---------------------------------------------------------------------------
#define STAGE_B 36864
#define SM_REQ  (2 * STAGE_B)

__global__ __launch_bounds__(128, 2)
void cofe_mma(const float* __restrict__ x, float* __restrict__ part) {
    extern __shared__ char smraw[];
    const uint32_t smem = smem_u32(smraw);

    const int tid  = threadIdx.x;
    const int lane = tid & 31;
    const int wid  = tid >> 5;
    const int wr   = wid >> 1;          // warp row (0,1) -> 48 rows each
    const int wc   = wid & 1;           // warp col (0,1) -> 96 cols each

    const int bx  = blockIdx.x;
    const int s   = bx & 3;             // k-split
    const int mt  = (bx >> 2) & 1;      // M tile (0: rows 0-95, 1: 96-191)
    const int g   = bx >> 3;            // 0..79
    const int b   = g / 5, off = g % 5;
    const int dy  = (off < 3) ? -1 : 0;
    const int dx  = (off < 3) ? (off - 1) : ((off == 3) ? -1 : 0);

    const int cA0   = mt * 96;
    const int kbase = s * KPER;
    const float* xb = x + (size_t)b * C_ * HW_;
    const float* xA = xb + (size_t)cA0 * HW_;

    // ---- per-lane constants ----
    const int mrel  = (lane & 7) + ((lane >> 3) & 1) * 8;  // A ldsm row-in-frag
    const int kcsA  = lane >> 4;                            // A ldsm chunk sel
    const int nrel  = (lane & 7) + (lane >> 4) * 8;         // B ldsm row-in-frag
    const int kcsB  = (lane >> 3) & 1;                      // B ldsm chunk sel
    const int klane = lane & 7;

    float acc[3][12][4];
#pragma unroll
    for (int i = 0; i < 3; i++)
#pragma unroll
        for (int j = 0; j < 12; j++)
#pragma unroll
            for (int r = 0; r < 4; r++) acc[i][j][r] = 0.f;

    // ---- fill helpers ----
    auto fillA = [&](int st, int kglob) {
        uint32_t smA = smem + st * STAGE_B;
#pragma unroll
        for (int i = 0; i < 6; i++) {
            int c  = tid + 128 * i;
            int m  = c >> 3, kc = c & 7;
            uint32_t dst = smA + m * 128 + ((kc ^ (m & 7)) << 4);
            cp_async16(dst, xA + (size_t)m * HW_ + kglob + kc * 4);
        }
    };
    auto fillB = [&](int st, int kglob) {
        uint32_t smB = smem + st * STAGE_B + 12288;
        int y  = kglob >> 6;
        int py = (y + dy < 0) ? 0 : (y + dy);
        int cc = (kglob & 63) + dx + lane;
        cc = (cc < 0) ? 0 : ((cc > 63) ? 63 : cc);
        const float* src = xb + py * 64 + cc;
        uint32_t dbase = smB + ((lane & 3) << 2);
#pragma unroll
        for (int r0 = 0; r0 < 48; r0 += 8) {
            float v[8];
#pragma unroll
            for (int j = 0; j < 8; j++) {
                int n = wid + 4 * (r0 + j);
                v[j] = __ldg(src + (size_t)n * HW_);
            }
#pragma unroll
            for (int j = 0; j < 8; j++) {
                int n = wid + 4 * (r0 + j);
                sts32(dbase + n * 128 + (((lane >> 2) ^ (n & 7)) << 4), v[j]);
            }
        }
    };

    // ---- prologue ----
    fillB(0, kbase);
    fillA(0, kbase);
    cp_commit();

    // ---- main loop ----
    for (int kt = 0; kt < NKT; kt++) {
        int st = kt & 1;
        __syncthreads();                    // prev compute done -> safe to refill
        if (kt + 1 < NKT) {
            int kn = kbase + (kt + 1) * 32;
            fillB(st ^ 1, kn);
            fillA(st ^ 1, kn);
            cp_commit();
            cp_wait<1>();                   // current stage A resident
        } else {
            cp_wait<0>();
        }
        __syncthreads();                    // fills visible to all warps

        uint32_t smA = smem + st * STAGE_B;
        uint32_t smB = smA + 12288;
        uint32_t aA0 = smA + (wr * 48 + mrel) * 128;
        uint32_t aB0 = smB + (wc * 96 + nrel) * 128;

#pragma unroll
        for (int ks = 0; ks < 4; ks++) {
            uint32_t af[3][4], bf[6][4];
#pragma unroll
            for (int i = 0; i < 3; i++) {
                uint32_t addr = aA0 + i * (16 * 128) +
                                (((ks * 2 + kcsA) ^ klane) << 4);
                ldsm4(af[i], addr);
            }
#pragma unroll
            for (int t = 0; t < 6; t++) {
                uint32_t addr = aB0 + t * (16 * 128) +
                                (((ks * 2 + kcsB) ^ klane) << 4);
                ldsm4(bf[t], addr);
            }
#pragma unroll
            for (int i = 0; i < 3; i++)
#pragma unroll
                for (int r = 0; r < 4; r++) af[i][r] = to_tf32(af[i][r]);
#pragma unroll
            for (int t = 0; t < 6; t++)
#pragma unroll
                for (int r = 0; r < 4; r++) bf[t][r] = to_tf32(bf[t][r]);
#pragma unroll
            for (int i = 0; i < 3; i++)
#pragma unroll
                for (int j = 0; j < 12; j++)
                    mma8(acc[i][j], af[i], &bf[j >> 1][(j & 1) * 2]);
        }
    }

    // ---- epilogue: write partial tile ----
    float* po = part + ((size_t)s * 80 + g) * NOUT;
    const int rA = lane >> 2, cB = (lane & 3) * 2;
#pragma unroll
    for (int i = 0; i < 3; i++) {
        int c0 = cA0 + wr * 48 + i * 16 + rA;
#pragma unroll
        for (int j = 0; j < 12; j++) {
            int d0 = wc * 96 + j * 8 + cB;
            *reinterpret_cast<float2*>(po + (size_t)c0 * C_ + d0) =
                make_float2(acc[i][j][0], acc[i][j][1]);
            *reinterpret_cast<float2*>(po + (size_t)(c0 + 8) * C_ + d0) =
                make_float2(acc[i][j][2], acc[i][j][3]);
        }
    }
}

// ---------------------------------------------------------------------------
// reduce 4 k-split partials + L2 normalize -> out
// ---------------------------------------------------------------------------
__global__ __launch_bounds__(512) void cofe_norm(const float* __restrict__ part,
                                                 float* __restrict__ out) {
    const int g = blockIdx.x;
    const float4* p0 = reinterpret_cast<const float4*>(part + (size_t)g * NOUT);
    const float4* p1 = reinterpret_cast<const float4*>(part + ((size_t)80 + g) * NOUT);
    const float4* p2 = reinterpret_cast<const float4*>(part + ((size_t)160 + g) * NOUT);
    const float4* p3 = reinterpret_cast<const float4*>(part + ((size_t)240 + g) * NOUT);
    float4* o4 = reinterpret_cast<float4*>(out + (size_t)g * NOUT);
    const int tid = threadIdx.x;

    float ss = 0.f;
#pragma unroll 2
    for (int i = tid; i < NOUT / 4; i += 512) {
        float4 a = p0[i], bq = p1[i], c = p2[i], d = p3[i];
        float4 v = make_float4(a.x + bq.x + c.x + d.x, a.y + bq.y + c.y + d.y,
                               a.z + bq.z + c.z + d.z, a.w + bq.w + c.w + d.w);
        ss += v.x * v.x + v.y * v.y + v.z * v.z + v.w * v.w;
        o4[i] = v;
    }
    __shared__ float red[16];
#pragma unroll
    for (int d = 16; d > 0; d >>= 1) ss += __shfl_xor_sync(0xffffffffu, ss, d);
    if ((tid & 31) == 0) red[tid >> 5] = ss;
    __syncthreads();
    if (tid < 32) {
        float v = (tid < 16) ? red[tid] : 0.f;
#pragma unroll
        for (int d = 8; d > 0; d >>= 1) v += __shfl_xor_sync(0xffffffffu, v, d);
        if (tid == 0) red[0] = v;
    }
    __syncthreads();
    const float scale = 1.0f / fmaxf(sqrtf(red[0]), 1e-12f);

#pragma unroll 2
    for (int i = tid; i < NOUT / 4; i += 512) {
        float4 v = o4[i];
        v.x *= scale; v.y *= scale; v.z *= scale; v.w *= scale;
        o4[i] = v;
    }
}

// ---------------------------------------------------------------------------
extern "C" void kernel_launch(void* const* d_in, const int* in_sizes, int n_in,
                              void* d_out, int out_size) {
    const float* x = (const float*)d_in[0];
    float* out = (float*)d_out;

    float* part = nullptr;
    cudaGetSymbolAddress((void**)&part, g_part);

    cudaFuncSetAttribute(cofe_mma, cudaFuncAttributeMaxDynamicSharedMemorySize, SM_REQ);
    cofe_mma<<<640, 128, SM_REQ>>>(x, part);
    cofe_norm<<<80, 512>>>(part, out);
}

// round 4
// speedup vs baseline: 4.8250x; 1.0132x over previous
#include <cuda_runtime.h>
#include <cstdint>

#define B_    16
#define C_    192
#define HW_   4096
#define NOUT  (C_*C_)
#define KSPLIT 8
#define KPER   (HW_/KSPLIT)     // 512
#define NKT    (KPER/32)        // 16 k-tiles per CTA

__device__ float g_sums[80];

// ---------------------------------------------------------------------------
__device__ __forceinline__ uint32_t smem_u32(const void* p) {
    uint32_t a;
    asm("{ .reg .u64 t; cvta.to.shared.u64 t, %1; cvt.u32.u64 %0, t; }" : "=r"(a) : "l"(p));
    return a;
}
__device__ __forceinline__ void cp_async16(uint32_t dst, const void* src) {
    asm volatile("cp.async.cg.shared.global [%0], [%1], 16;" :: "r"(dst), "l"(src) : "memory");
}
__device__ __forceinline__ void cp_async4(uint32_t dst, const void* src) {
    asm volatile("cp.async.ca.shared.global [%0], [%1], 4;" :: "r"(dst), "l"(src) : "memory");
}
__device__ __forceinline__ void cp_commit() {
    asm volatile("cp.async.commit_group;" ::: "memory");
}
template <int N>
__device__ __forceinline__ void cp_wait() {
    asm volatile("cp.async.wait_group %0;" :: "n"(N) : "memory");
}
__device__ __forceinline__ void ldsm4(uint32_t* r, uint32_t addr) {
    asm volatile("ldmatrix.sync.aligned.m8n8.x4.shared.b16 {%0,%1,%2,%3}, [%4];"
                 : "=r"(r[0]), "=r"(r[1]), "=r"(r[2]), "=r"(r[3]) : "r"(addr));
}
__device__ __forceinline__ uint32_t to_tf32(uint32_t v) {
    uint32_t o;
    asm("cvt.rna.tf32.f32 %0, %1;" : "=r"(o) : "f"(__uint_as_float(v)));
    return o;
}
__device__ __forceinline__ void mma8(float* d, const uint32_t* a, const uint32_t* b) {
    asm volatile("mma.sync.aligned.m16n8k8.row.col.f32.tf32.tf32.f32 "
                 "{%0,%1,%2,%3}, {%4,%5,%6,%7}, {%8,%9}, {%0,%1,%2,%3};"
                 : "+f"(d[0]), "+f"(d[1]), "+f"(d[2]), "+f"(d[3])
                 : "r"(a[0]), "r"(a[1]), "r"(a[2]), "r"(a[3]), "r"(b[0]), "r"(b[1]));
}

// ---------------------------------------------------------------------------
// GEMM: CTA tile M=96, N=192, K=512 (one split). 128 threads = 4 warps (2x2),
// warp tile 48x96, tf32 mma.sync m16n8k8. All fills via cp.async.
// smem per stage: A 96x128B (12288) + B 192x128B (24576) = 36864B, 2 stages.
// swizzle: byte(row, chunk, j) = row*128 + ((chunk ^ (row&7))<<4) + j*4
// Epilogue: RED (atomicAdd) straight into out[g].
// ---------------------------------------------------------------------------
#define STAGE_B 36864
#define SM_REQ  (2 * STAGE_B)

__global__ __launch_bounds__(128, 2)
void cofe_mma(const float* __restrict__ x, float* __restrict__ out) {
    extern __shared__ char smraw[];
    const uint32_t smem = smem_u32(smraw);

    const int tid  = threadIdx.x;
    const int lane = tid & 31;
    const int wid  = tid >> 5;
    const int wr   = wid >> 1;
    const int wc   = wid & 1;

    const int bx  = blockIdx.x;
    const int s   = bx & 7;             // k-split (8)
    const int mt  = (bx >> 3) & 1;      // M tile
    const int g   = bx >> 4;            // 0..79
    const int b   = g / 5, off = g % 5;
    const int dy  = (off < 3) ? -1 : 0;
    const int dx  = (off < 3) ? (off - 1) : ((off == 3) ? -1 : 0);

    const int cA0   = mt * 96;
    const int kbase = s * KPER;
    const float* xb = x + (size_t)b * C_ * HW_;
    const float* xA = xb + (size_t)cA0 * HW_;

    const int mrel  = (lane & 7) + ((lane >> 3) & 1) * 8;
    const int kcsA  = lane >> 4;
    const int nrel  = (lane & 7) + (lane >> 4) * 8;
    const int kcsB  = (lane >> 3) & 1;
    const int klane = lane & 7;

    float acc[3][12][4];
#pragma unroll
    for (int i = 0; i < 3; i++)
#pragma unroll
        for (int j = 0; j < 12; j++)
#pragma unroll
            for (int r = 0; r < 4; r++) acc[i][j][r] = 0.f;

    // ---- fill helpers (all async) ----
    auto fillA = [&](int st, int kglob) {
        uint32_t smA = smem + st * STAGE_B;
#pragma unroll
        for (int i = 0; i < 6; i++) {
            int c  = tid + 128 * i;
            int m  = c >> 3, kc = c & 7;
            uint32_t dst = smA + m * 128 + ((kc ^ (m & 7)) << 4);
            cp_async16(dst, xA + (size_t)m * HW_ + kglob + kc * 4);
        }
    };
    auto fillB = [&](int st, int kglob) {
        uint32_t smB = smem + st * STAGE_B + 12288;
        int y   = kglob >> 6;
        int xx0 = kglob & 63;
        int py  = y + dy; if (py < 0) py = 0;
        const float* rowb = xb + py * 64;
        if (dx == 0) {
#pragma unroll
            for (int i = 0; i < 12; i++) {
                int q = i * 128 + tid;
                int n = q >> 3, kc = q & 7;
                uint32_t dst = smB + n * 128 + ((kc ^ (n & 7)) << 4);
                cp_async16(dst, rowb + (size_t)n * HW_ + xx0 + kc * 4);
            }
        } else {
#pragma unroll
            for (int i = 0; i < 12; i++) {
                int q = i * 128 + tid;
                int n = q >> 3, kc = q & 7;
                uint32_t dst = smB + n * 128 + ((kc ^ (n & 7)) << 4);
                const float* srcn = rowb + (size_t)n * HW_;
#pragma unroll
                for (int e = 0; e < 4; e++) {
                    int px = xx0 + kc * 4 + e + dx;
                    px = (px < 0) ? 0 : ((px > 63) ? 63 : px);
                    cp_async4(dst + e * 4, srcn + px);
                }
            }
        }
    };

    // ---- prologue ----
    fillB(0, kbase);
    fillA(0, kbase);
    cp_commit();

    // ---- main loop ----
    for (int kt = 0; kt < NKT; kt++) {
        int st = kt & 1;
        __syncthreads();                    // prev consume done -> refill safe
        if (kt + 1 < NKT) {
            int kn = kbase + (kt + 1) * 32;
            fillB(st ^ 1, kn);
            fillA(st ^ 1, kn);
            cp_commit();
            cp_wait<1>();                   // current stage resident
        } else {
            cp_wait<0>();
        }
        __syncthreads();

        uint32_t smA = smem + st * STAGE_B;
        uint32_t smB = smA + 12288;
        uint32_t aA0 = smA + (wr * 48 + mrel) * 128;
        uint32_t aB0 = smB + (wc * 96 + nrel) * 128;

#pragma unroll
        for (int ks = 0; ks < 4; ks++) {
            uint32_t af[3][4], bf[6][4];
#pragma unroll
            for (int i = 0; i < 3; i++)
                ldsm4(af[i], aA0 + i * (16 * 128) + (((ks * 2 + kcsA) ^ klane) << 4));
#pragma unroll
            for (int t = 0; t < 6; t++)
                ldsm4(bf[t], aB0 + t * (16 * 128) + (((ks * 2 + kcsB) ^ klane) << 4));
#pragma unroll
            for (int i = 0; i < 3; i++)
#pragma unroll
                for (int r = 0; r < 4; r++) af[i][r] = to_tf32(af[i][r]);
#pragma unroll
            for (int t = 0; t < 6; t++)
#pragma unroll
                for (int r = 0; r < 4; r++) bf[t][r] = to_tf32(bf[t][r]);
#pragma unroll
            for (int i = 0; i < 3; i++)
#pragma unroll
                for (int j = 0; j < 12; j++)
                    mma8(acc[i][j], af[i], &bf[j >> 1][(j & 1) * 2]);
        }
    }

    // ---- epilogue: RED into out[g] ----
    float* po = out + (size_t)g * NOUT;
    const int rA = lane >> 2, cB = (lane & 3) * 2;
#pragma unroll
    for (int i = 0; i < 3; i++) {
        int c0 = cA0 + wr * 48 + i * 16 + rA;
#pragma unroll
        for (int j = 0; j < 12; j++) {
            int d0 = wc * 96 + j * 8 + cB;
            atomicAdd(po + (size_t)c0 * C_ + d0,     acc[i][j][0]);
            atomicAdd(po + (size_t)c0 * C_ + d0 + 1, acc[i][j][1]);
            atomicAdd(po + (size_t)(c0 + 8) * C_ + d0,     acc[i][j][2]);
            atomicAdd(po + (size_t)(c0 + 8) * C_ + d0 + 1, acc[i][j][3]);
        }
    }
}

// ---------------------------------------------------------------------------
// zero-init: out (80*36864 floats) + g_sums
// ---------------------------------------------------------------------------
__global__ __launch_bounds__(1024) void cofe_zero(float* __restrict__ out) {
    int i = blockIdx.x * 1024 + threadIdx.x;              // 720 blocks exact
    reinterpret_cast<float4*>(out)[i] = make_float4(0.f, 0.f, 0.f, 0.f);
    if (blockIdx.x == 0 && threadIdx.x < 80) g_sums[threadIdx.x] = 0.f;
}

// ---------------------------------------------------------------------------
// norm pass 1: partial square-sums (grid 80*8)
// ---------------------------------------------------------------------------
__global__ __launch_bounds__(256) void cofe_norm1(const float* __restrict__ out) {
    const int g = blockIdx.x >> 3, seg = blockIdx.x & 7;
    const float4* p = reinterpret_cast<const float4*>(out + (size_t)g * NOUT + seg * 4608);
    const int tid = threadIdx.x;
    float ss = 0.f;
#pragma unroll
    for (int i = tid; i < 1152; i += 256) {
        float4 v = p[i];
        ss += v.x * v.x + v.y * v.y + v.z * v.z + v.w * v.w;
    }
    __shared__ float red[8];
#pragma unroll
    for (int d = 16; d > 0; d >>= 1) ss += __shfl_xor_sync(0xffffffffu, ss, d);
    if ((tid & 31) == 0) red[tid >> 5] = ss;
    __syncthreads();
    if (tid < 32) {
        float v = (tid < 8) ? red[tid] : 0.f;
#pragma unroll
        for (int d = 4; d > 0; d >>= 1) v += __shfl_xor_sync(0xffffffffu, v, d);
        if (tid == 0) atomicAdd(&g_sums[g], v);
    }
}

// ---------------------------------------------------------------------------
// norm pass 2: scale (grid 80*8)
// ---------------------------------------------------------------------------
__global__ __launch_bounds__(256) void cofe_norm2(float* __restrict__ out) {
    const int g = blockIdx.x >> 3, seg = blockIdx.x & 7;
    float4* p = reinterpret_cast<float4*>(out + (size_t)g * NOUT + seg * 4608);
    const float scale = 1.0f / fmaxf(sqrtf(g_sums[g]), 1e-12f);
    const int tid = threadIdx.x;
#pragma unroll
    for (int i = tid; i < 1152; i += 256) {
        float4 v = p[i];
        v.x *= scale; v.y *= scale; v.z *= scale; v.w *= scale;
        p[i] = v;
    }
}

// ---------------------------------------------------------------------------
extern "C" void kernel_launch(void* const* d_in, const int* in_sizes, int n_in,
                              void* d_out, int out_size) {
    const float* x = (const float*)d_in[0];
    float* out = (float*)d_out;

    cofe_zero<<<720, 1024>>>(out);
    cudaFuncSetAttribute(cofe_mma, cudaFuncAttributeMaxDynamicSharedMemorySize, SM_REQ);
    cofe_mma<<<1280, 128, SM_REQ>>>(x, out);
    cofe_norm1<<<640, 256>>>(out);
    cofe_norm2<<<640, 256>>>(out);
}

// round 5
// speedup vs baseline: 7.9046x; 1.6383x over previous
#include <cuda_runtime.h>
#include <cuda_fp16.h>
#include <cstdint>

#define B_    16
#define C_    192
#define HW_   4096
#define NOUT  (C_*C_)
#define KSPLIT 8
#define KPER   (HW_/KSPLIT)     // 512
#define NKT    (KPER/64)        // 8 k-tiles (64 k each = one image row)

__device__ float g_sums[80];
// fp16 copies: variant v: 0 -> dx=-1, 1 -> dx=0, 2 -> dx=+1  (edge-clamped in x)
__device__ __half g_xh[(size_t)3 * B_ * C_ * HW_];

// ---------------------------------------------------------------------------
__device__ __forceinline__ uint32_t smem_u32(const void* p) {
    uint32_t a;
    asm("{ .reg .u64 t; cvta.to.shared.u64 t, %1; cvt.u32.u64 %0, t; }" : "=r"(a) : "l"(p));
    return a;
}
__device__ __forceinline__ void cp_async16(uint32_t dst, const void* src) {
    asm volatile("cp.async.cg.shared.global [%0], [%1], 16;" :: "r"(dst), "l"(src) : "memory");
}
__device__ __forceinline__ void cp_commit() {
    asm volatile("cp.async.commit_group;" ::: "memory");
}
template <int N>
__device__ __forceinline__ void cp_wait() {
    asm volatile("cp.async.wait_group %0;" :: "n"(N) : "memory");
}
__device__ __forceinline__ void ldsm4(uint32_t* r, uint32_t addr) {
    asm volatile("ldmatrix.sync.aligned.m8n8.x4.shared.b16 {%0,%1,%2,%3}, [%4];"
                 : "=r"(r[0]), "=r"(r[1]), "=r"(r[2]), "=r"(r[3]) : "r"(addr));
}
__device__ __forceinline__ void mma16(float* d, const uint32_t* a, const uint32_t* b) {
    asm volatile("mma.sync.aligned.m16n8k16.row.col.f32.f16.f16.f32 "
                 "{%0,%1,%2,%3}, {%4,%5,%6,%7}, {%8,%9}, {%0,%1,%2,%3};"
                 : "+f"(d[0]), "+f"(d[1]), "+f"(d[2]), "+f"(d[3])
                 : "r"(a[0]), "r"(a[1]), "r"(a[2]), "r"(a[3]), "r"(b[0]), "r"(b[1]));
}

// ---------------------------------------------------------------------------
// prep: fp16-convert x into 3 dx-shifted variants (dy handled at fill time).
// thread handles one (row, quad of 4 px). 196608 rows x 16 quads.
// ---------------------------------------------------------------------------
__global__ __launch_bounds__(256) void cofe_prep(const float* __restrict__ x) {
    int idx = blockIdx.x * 256 + threadIdx.x;     // 12288 * 256 = 3,145,728
    int row = idx >> 4;                            // (b*C + c)*64 + y
    int q   = idx & 15;
    const float* src = x + (size_t)row * 64 + q * 4;
    float4 v = *reinterpret_cast<const float4*>(src);
    float lm = (q == 0)  ? v.x : src[-1];
    float rp = (q == 15) ? v.w : src[4];

    size_t o = (size_t)row * 64 + q * 4;
    const size_t VS = (size_t)B_ * C_ * HW_;
    __half2* d0 = reinterpret_cast<__half2*>(g_xh + o);            // dx=-1
    __half2* d1 = reinterpret_cast<__half2*>(g_xh + VS + o);       // dx=0
    __half2* d2 = reinterpret_cast<__half2*>(g_xh + 2 * VS + o);   // dx=+1
    d0[0] = __floats2half2_rn(lm,  v.x); d0[1] = __floats2half2_rn(v.y, v.z);
    d1[0] = __floats2half2_rn(v.x, v.y); d1[1] = __floats2half2_rn(v.z, v.w);
    d2[0] = __floats2half2_rn(v.y, v.z); d2[1] = __floats2half2_rn(v.w, rp);
}

// ---------------------------------------------------------------------------
// GEMM: CTA tile M=96, N=192, K=512 (one split), fp16 HMMA m16n8k16.
// 128 threads = 4 warps (2x2), warp tile 48x96, k-tile 64 (=128B rows fp16).
// smem/stage: A 96x128B + B 192x128B = 36864B, 2 stages.
// swizzle: byte(row, chunk16B, j) = row*128 + ((chunk ^ (row&7))<<4)
// Epilogue: RED (atomicAdd) into out[g].
// ---------------------------------------------------------------------------
#define STAGE_B 36864
#define SM_REQ  (2 * STAGE_B)

__global__ __launch_bounds__(128, 2)
void cofe_mma(float* __restrict__ out) {
    extern __shared__ char smraw[];
    const uint32_t smem = smem_u32(smraw);

    const int tid  = threadIdx.x;
    const int lane = tid & 31;
    const int wid  = tid >> 5;
    const int wr   = wid >> 1;
    const int wc   = wid & 1;

    const int bx  = blockIdx.x;
    const int s   = bx & 7;             // k-split
    const int mt  = (bx >> 3) & 1;      // M tile
    const int g   = bx >> 4;            // 0..79
    const int b   = g / 5, off = g % 5;
    const int dy  = (off < 3) ? -1 : 0;
    const int dx  = (off < 3) ? (off - 1) : ((off == 3) ? -1 : 0);

    const int cA0 = mt * 96;
    const int y0  = s * (KPER / 64);    // first image row of this split
    const size_t VS = (size_t)B_ * C_ * HW_;
    const __half* xAh = g_xh + VS + ((size_t)(b * C_ + cA0)) * HW_;      // dx=0 variant
    const __half* xBh = g_xh + (size_t)(dx + 1) * VS + (size_t)(b * C_) * HW_;

    const int mrel  = (lane & 7) + ((lane >> 3) & 1) * 8;
    const int kcsA  = lane >> 4;
    const int nrel  = (lane & 7) + (lane >> 4) * 8;
    const int kcsB  = (lane >> 3) & 1;
    const int klane = lane & 7;

    float acc[3][12][4];
#pragma unroll
    for (int i = 0; i < 3; i++)
#pragma unroll
        for (int j = 0; j < 12; j++)
#pragma unroll
            for (int r = 0; r < 4; r++) acc[i][j][r] = 0.f;

    // ---- fills: k-tile = image row y; 16B chunk = 8 halves ----
    auto fillA = [&](int st, int y) {
        uint32_t smA = smem + st * STAGE_B;
#pragma unroll
        for (int i = 0; i < 6; i++) {
            int c  = tid + 128 * i;
            int m  = c >> 3, kc = c & 7;
            uint32_t dst = smA + m * 128 + ((kc ^ (m & 7)) << 4);
            cp_async16(dst, xAh + (size_t)m * HW_ + (y << 6) + kc * 8);
        }
    };
    auto fillB = [&](int st, int y) {
        uint32_t smB = smem + st * STAGE_B + 12288;
        int py = y + dy; if (py < 0) py = 0;
#pragma unroll
        for (int i = 0; i < 12; i++) {
            int q = i * 128 + tid;
            int n = q >> 3, kc = q & 7;
            uint32_t dst = smB + n * 128 + ((kc ^ (n & 7)) << 4);
            cp_async16(dst, xBh + (size_t)n * HW_ + (py << 6) + kc * 8);
        }
    };

    // ---- prologue ----
    fillB(0, y0);
    fillA(0, y0);
    cp_commit();

    // ---- main loop ----
    for (int kt = 0; kt < NKT; kt++) {
        int st = kt & 1;
        __syncthreads();
        if (kt + 1 < NKT) {
            fillB(st ^ 1, y0 + kt + 1);
            fillA(st ^ 1, y0 + kt + 1);
            cp_commit();
            cp_wait<1>();
        } else {
            cp_wait<0>();
        }
        __syncthreads();

        uint32_t smA = smem + st * STAGE_B;
        uint32_t smB = smA + 12288;
        uint32_t aA0 = smA + (wr * 48 + mrel) * 128;
        uint32_t aB0 = smB + (wc * 96 + nrel) * 128;

#pragma unroll
        for (int ks = 0; ks < 4; ks++) {        // k16 per step, 4 steps = k64
            uint32_t af[3][4], bf[6][4];
#pragma unroll
            for (int i = 0; i < 3; i++)
                ldsm4(af[i], aA0 + i * (16 * 128) + (((ks * 2 + kcsA) ^ klane) << 4));
#pragma unroll
            for (int t = 0; t < 6; t++)
                ldsm4(bf[t], aB0 + t * (16 * 128) + (((ks * 2 + kcsB) ^ klane) << 4));
#pragma unroll
            for (int i = 0; i < 3; i++)
#pragma unroll
                for (int j = 0; j < 12; j++)
                    mma16(acc[i][j], af[i], &bf[j >> 1][(j & 1) * 2]);
        }
    }

    // ---- epilogue: RED into out[g] ----
    float* po = out + (size_t)g * NOUT;
    const int rA = lane >> 2, cB = (lane & 3) * 2;
#pragma unroll
    for (int i = 0; i < 3; i++) {
        int c0 = cA0 + wr * 48 + i * 16 + rA;
#pragma unroll
        for (int j = 0; j < 12; j++) {
            int d0 = wc * 96 + j * 8 + cB;
            atomicAdd(po + (size_t)c0 * C_ + d0,     acc[i][j][0]);
            atomicAdd(po + (size_t)c0 * C_ + d0 + 1, acc[i][j][1]);
            atomicAdd(po + (size_t)(c0 + 8) * C_ + d0,     acc[i][j][2]);
            atomicAdd(po + (size_t)(c0 + 8) * C_ + d0 + 1, acc[i][j][3]);
        }
    }
}

// ---------------------------------------------------------------------------
__global__ __launch_bounds__(1024) void cofe_zero(float* __restrict__ out) {
    int i = blockIdx.x * 1024 + threadIdx.x;              // 720 blocks exact
    reinterpret_cast<float4*>(out)[i] = make_float4(0.f, 0.f, 0.f, 0.f);
    if (blockIdx.x == 0 && threadIdx.x < 80) g_sums[threadIdx.x] = 0.f;
}

__global__ __launch_bounds__(256) void cofe_norm1(const float* __restrict__ out) {
    const int g = blockIdx.x >> 3, seg = blockIdx.x & 7;
    const float4* p = reinterpret_cast<const float4*>(out + (size_t)g * NOUT + seg * 4608);
    const int tid = threadIdx.x;
    float ss = 0.f;
#pragma unroll
    for (int i = tid; i < 1152; i += 256) {
        float4 v = p[i];
        ss += v.x * v.x + v.y * v.y + v.z * v.z + v.w * v.w;
    }
    __shared__ float red[8];
#pragma unroll
    for (int d = 16; d > 0; d >>= 1) ss += __shfl_xor_sync(0xffffffffu, ss, d);
    if ((tid & 31) == 0) red[tid >> 5] = ss;
    __syncthreads();
    if (tid < 32) {
        float v = (tid < 8) ? red[tid] : 0.f;
#pragma unroll
        for (int d = 4; d > 0; d >>= 1) v += __shfl_xor_sync(0xffffffffu, v, d);
        if (tid == 0) atomicAdd(&g_sums[g], v);
    }
}

__global__ __launch_bounds__(256) void cofe_norm2(float* __restrict__ out) {
    const int g = blockIdx.x >> 3, seg = blockIdx.x & 7;
    float4* p = reinterpret_cast<float4*>(out + (size_t)g * NOUT + seg * 4608);
    const float scale = 1.0f / fmaxf(sqrtf(g_sums[g]), 1e-12f);
    const int tid = threadIdx.x;
#pragma unroll
    for (int i = tid; i < 1152; i += 256) {
        float4 v = p[i];
        v.x *= scale; v.y *= scale; v.z *= scale; v.w *= scale;
        p[i] = v;
    }
}

// ---------------------------------------------------------------------------
extern "C" void kernel_launch(void* const* d_in, const int* in_sizes, int n_in,
                              void* d_out, int out_size) {
    const float* x = (const float*)d_in[0];
    float* out = (float*)d_out;

    cofe_zero<<<720, 1024>>>(out);
    cofe_prep<<<12288, 256>>>(x);
    cudaFuncSetAttribute(cofe_mma, cudaFuncAttributeMaxDynamicSharedMemorySize, SM_REQ);
    cofe_mma<<<1280, 128, SM_REQ>>>(out);
    cofe_norm1<<<640, 256>>>(out);
    cofe_norm2<<<640, 256>>>(out);
}